// round 1
// baseline (speedup 1.0000x reference)
#include <cuda_runtime.h>
#include <cuda_bf16.h>
#include <cstdint>

// ---------------------------------------------------------------------------
// Shifted Window Attention (Swin), B=32 H=W=56 C=256, 7x7 windows, shift 3,
// 8 heads, head_dim=32. No padding needed (56 % 7 == 0), always shifted.
//
// Pipeline:
//   1) QKV GEMM:  g_qkv[M,768] = x[M,256] @ qkv_w[768,256]^T + qkv_b
//   2) attention per (window, head), gather rows with roll folded into the
//      index math; writes g_att[M,256] back at ORIGINAL coordinates (the
//      inverse roll cancels the forward roll).
//   3) proj GEMM: out[M,256] = g_att[M,256] @ proj_w[256,256]^T + proj_b
// ---------------------------------------------------------------------------

#define M_ROWS 100352           // 32*56*56
#define C_DIM  256

__device__ float g_qkv[100352ULL * 768];   // 308 MB scratch
__device__ float g_att[100352ULL * 256];   // 103 MB scratch

// ---- packed f32x2 helpers --------------------------------------------------
__device__ __forceinline__ unsigned long long pk2(float x) {
    unsigned long long r;
    unsigned u = __float_as_uint(x);
    asm("mov.b64 %0, {%1, %1};" : "=l"(r) : "r"(u));
    return r;
}
__device__ __forceinline__ void ffma2(unsigned long long& d,
                                      unsigned long long a,
                                      unsigned long long b) {
    asm("fma.rn.f32x2 %0, %1, %2, %0;" : "+l"(d) : "l"(a), "l"(b));
}
__device__ __forceinline__ float lo32(unsigned long long v) {
    return __uint_as_float((unsigned)v);
}
__device__ __forceinline__ float hi32(unsigned long long v) {
    return __uint_as_float((unsigned)(v >> 32));
}

// ---------------------------------------------------------------------------
// GEMM: C[M,N] = A[M,K] @ W[N,K]^T + bias[N]
// BM=BN=128, BK=16, 256 threads, 8x8 per thread via f32x2 (8 x 4 pairs).
// Requires M%128==0, N%128==0, K%16==0 (true here: M=100352, N in {768,256}, K=256)
// ---------------------------------------------------------------------------
__global__ void __launch_bounds__(256, 2)
gemm_f32x2(const float* __restrict__ A, const float* __restrict__ W,
           const float* __restrict__ bias, float* __restrict__ C,
           int K, int N) {
    __shared__ float As[16][128];
    __shared__ float Ws[16][128];

    const int tid = threadIdx.x;
    const int tr  = tid >> 4;        // 0..15 (row group)
    const int tc  = tid & 15;        // 0..15 (col group)
    const size_t m0 = (size_t)blockIdx.y * 128;
    const int    n0 = blockIdx.x * 128;

    unsigned long long acc[8][4];
#pragma unroll
    for (int i = 0; i < 8; i++)
#pragma unroll
        for (int j = 0; j < 4; j++) acc[i][j] = 0ULL;

    const int lm = tid >> 2;          // 0..63
    const int lk = (tid & 3) << 2;    // 0,4,8,12
    const float* Aptr = A + (m0 + lm) * (size_t)K + lk;
    const float* Wptr = W + (size_t)(n0 + lm) * K + lk;

    for (int k0 = 0; k0 < K; k0 += 16) {
        float4 a0 = *(const float4*)(Aptr + k0);
        float4 a1 = *(const float4*)(Aptr + k0 + (size_t)64 * K);
        float4 w0 = *(const float4*)(Wptr + k0);
        float4 w1 = *(const float4*)(Wptr + k0 + (size_t)64 * K);

        As[lk + 0][lm] = a0.x; As[lk + 1][lm] = a0.y;
        As[lk + 2][lm] = a0.z; As[lk + 3][lm] = a0.w;
        As[lk + 0][lm + 64] = a1.x; As[lk + 1][lm + 64] = a1.y;
        As[lk + 2][lm + 64] = a1.z; As[lk + 3][lm + 64] = a1.w;

        Ws[lk + 0][lm] = w0.x; Ws[lk + 1][lm] = w0.y;
        Ws[lk + 2][lm] = w0.z; Ws[lk + 3][lm] = w0.w;
        Ws[lk + 0][lm + 64] = w1.x; Ws[lk + 1][lm + 64] = w1.y;
        Ws[lk + 2][lm + 64] = w1.z; Ws[lk + 3][lm + 64] = w1.w;

        __syncthreads();

#pragma unroll
        for (int kk = 0; kk < 16; kk++) {
            float4 af0 = *(const float4*)&As[kk][tr * 8];
            float4 af1 = *(const float4*)&As[kk][tr * 8 + 4];
            const unsigned long long* wrow =
                (const unsigned long long*)&Ws[kk][tc * 8];
            unsigned long long bb0 = wrow[0], bb1 = wrow[1],
                               bb2 = wrow[2], bb3 = wrow[3];
            unsigned long long aa[8];
            aa[0] = pk2(af0.x); aa[1] = pk2(af0.y);
            aa[2] = pk2(af0.z); aa[3] = pk2(af0.w);
            aa[4] = pk2(af1.x); aa[5] = pk2(af1.y);
            aa[6] = pk2(af1.z); aa[7] = pk2(af1.w);
#pragma unroll
            for (int i = 0; i < 8; i++) {
                ffma2(acc[i][0], aa[i], bb0);
                ffma2(acc[i][1], aa[i], bb1);
                ffma2(acc[i][2], aa[i], bb2);
                ffma2(acc[i][3], aa[i], bb3);
            }
        }
        __syncthreads();
    }

    // epilogue
    float bn[8];
#pragma unroll
    for (int j = 0; j < 8; j++) bn[j] = bias[n0 + tc * 8 + j];

#pragma unroll
    for (int i = 0; i < 8; i++) {
        size_t m = m0 + tr * 8 + i;
        float* crow = C + m * (size_t)N + n0 + tc * 8;
        float v[8];
#pragma unroll
        for (int j = 0; j < 4; j++) {
            v[2 * j]     = lo32(acc[i][j]) + bn[2 * j];
            v[2 * j + 1] = hi32(acc[i][j]) + bn[2 * j + 1];
        }
        *(float4*)(crow)     = make_float4(v[0], v[1], v[2], v[3]);
        *(float4*)(crow + 4) = make_float4(v[4], v[5], v[6], v[7]);
    }
}

// ---------------------------------------------------------------------------
// Attention: one block per (window, head). 16384 blocks x 128 threads.
// ---------------------------------------------------------------------------
__global__ void __launch_bounds__(128)
attn_kernel(const float* __restrict__ qkv, const float* __restrict__ table,
            float* __restrict__ outp) {
    __shared__ float Qs[49][36];
    __shared__ float Ks[49][36];
    __shared__ float Vs[49][36];
    __shared__ float S[49][50];
    __shared__ float Bs[169];
    __shared__ int   rowi[49];

    const int tid  = threadIdx.x;
    const int blk  = blockIdx.x;
    const int head = blk & 7;
    const int w    = blk >> 3;            // window id 0..2047
    const int b    = w >> 6;              // batch
    const int wr   = (w >> 3) & 7;        // window row
    const int wc   = w & 7;               // window col

    if (tid < 49) {
        int ih = tid / 7, iw = tid - ih * 7;
        int hh = wr * 7 + ih;              // shifted-image coords
        int vv = wc * 7 + iw;
        int oh = hh + 3; if (oh >= 56) oh -= 56;   // original coords (roll)
        int ow = vv + 3; if (ow >= 56) ow -= 56;
        rowi[tid] = (b * 56 + oh) * 56 + ow;
    }
    for (int t = tid; t < 169; t += 128) Bs[t] = table[t * 8 + head];
    __syncthreads();

    // gather Q,K,V (49 x 32 each) for this head
    for (int idx = tid; idx < 392; idx += 128) {
        int p = idx >> 3, q = idx & 7;
        const float4* src =
            (const float4*)(qkv + (size_t)rowi[p] * 768 + head * 32) + q;
        *(float4*)&Qs[p][q * 4] = src[0];
        *(float4*)&Ks[p][q * 4] = src[64];    // +256 floats
        *(float4*)&Vs[p][q * 4] = src[128];   // +512 floats
    }
    __syncthreads();

    const float scale = 0.17677669529663687f;   // 1/sqrt(32)

    // S = scale*Q K^T + bias + mask   (thread t<98: row i = t/2, half of j)
    if (tid < 98) {
        int i = tid >> 1;
        int jbeg = (tid & 1) * 25;
        int jend = (tid & 1) ? 49 : 25;
        unsigned long long q2[16];
        const unsigned long long* qp = (const unsigned long long*)&Qs[i][0];
#pragma unroll
        for (int z = 0; z < 16; z++) q2[z] = qp[z];

        int ih = i / 7, iw = i - ih * 7;
        int hi_ = wr * 7 + ih, wi_ = wc * 7 + iw;
        int rhi = (hi_ < 49) ? 0 : (hi_ < 53 ? 1 : 2);
        int rwi = (wi_ < 49) ? 0 : (wi_ < 53 ? 1 : 2);

        for (int j = jbeg; j < jend; j++) {
            const unsigned long long* kp =
                (const unsigned long long*)&Ks[j][0];
            unsigned long long a = 0ULL;
#pragma unroll
            for (int z = 0; z < 16; z++) ffma2(a, q2[z], kp[z]);
            float s = (lo32(a) + hi32(a)) * scale;

            int jh = j / 7, jw = j - jh * 7;
            s += Bs[(ih - jh + 6) * 13 + (iw - jw + 6)];

            int hj = wr * 7 + jh, wj = wc * 7 + jw;
            int rhj = (hj < 49) ? 0 : (hj < 53 ? 1 : 2);
            int rwj = (wj < 49) ? 0 : (wj < 53 ? 1 : 2);
            if ((rhi != rhj) | (rwi != rwj)) s -= 100.0f;
            S[i][j] = s;
        }
    }
    __syncthreads();

    // softmax per row
    if (tid < 49) {
        float m = -1e30f;
#pragma unroll 7
        for (int j = 0; j < 49; j++) m = fmaxf(m, S[tid][j]);
        float sum = 0.f;
#pragma unroll 7
        for (int j = 0; j < 49; j++) {
            float e = __expf(S[tid][j] - m);
            S[tid][j] = e;
            sum += e;
        }
        float inv = 1.0f / sum;
#pragma unroll 7
        for (int j = 0; j < 49; j++) S[tid][j] *= inv;
    }
    __syncthreads();

    // O = P @ V  (thread t<98: row i = t/2, 16 of 32 dims)
    if (tid < 98) {
        int i  = tid >> 1;
        int dh = (tid & 1) * 16;
        unsigned long long o2[8];
#pragma unroll
        for (int z = 0; z < 8; z++) o2[z] = 0ULL;
        for (int j = 0; j < 49; j++) {
            unsigned long long ss = pk2(S[i][j]);
            const unsigned long long* vp =
                (const unsigned long long*)&Vs[j][dh];
#pragma unroll
            for (int z = 0; z < 8; z++) ffma2(o2[z], ss, vp[z]);
        }
        float* dst = outp + (size_t)rowi[i] * 256 + head * 32 + dh;
#pragma unroll
        for (int z = 0; z < 8; z++) {
            dst[2 * z]     = lo32(o2[z]);
            dst[2 * z + 1] = hi32(o2[z]);
        }
    }
}

// ---------------------------------------------------------------------------
extern "C" void kernel_launch(void* const* d_in, const int* in_sizes, int n_in,
                              void* d_out, int out_size) {
    const float* x      = (const float*)d_in[0];
    const float* qkv_w  = (const float*)d_in[1];
    const float* qkv_b  = (const float*)d_in[2];
    const float* proj_w = (const float*)d_in[3];
    const float* proj_b = (const float*)d_in[4];
    const float* table  = (const float*)d_in[5];
    float* out = (float*)d_out;

    void* qkv_p = nullptr;
    void* att_p = nullptr;
    cudaGetSymbolAddress(&qkv_p, g_qkv);
    cudaGetSymbolAddress(&att_p, g_att);
    float* qkv = (float*)qkv_p;
    float* att = (float*)att_p;

    // 1) QKV projection: M=100352, K=256, N=768
    dim3 gq(768 / 128, M_ROWS / 128);
    gemm_f32x2<<<gq, 256>>>(x, qkv_w, qkv_b, qkv, 256, 768);

    // 2) windowed attention: 2048 windows * 8 heads
    attn_kernel<<<2048 * 8, 128>>>(qkv, table, att);

    // 3) output projection: M=100352, K=256, N=256
    dim3 gp(256 / 128, M_ROWS / 128);
    gemm_f32x2<<<gp, 256>>>(att, proj_w, proj_b, out, 256, 256);
}

// round 3
// speedup vs baseline: 1.9517x; 1.9517x over previous
#include <cuda_runtime.h>
#include <cuda_fp16.h>
#include <cstdint>

// ---------------------------------------------------------------------------
// Swin shifted-window attention, B=32 H=W=56 C=256, 7x7 win, shift 3, 8 heads.
//
//  1) convert x -> x_cat fp16 [M,512] = [hi | lo]      (2-term K-split)
//     convert w -> w_cat fp16 [N,512] = [hi | hi]
//  2) QKV GEMM (mma.sync f16, fp32 acc): g_qkv[M,768] fp32
//  3) windowed attention (fp32 f32x2), writes acat fp16 [M,512] split layout
//     (cyclic roll folded into gather/scatter indices)
//  4) proj GEMM (mma.sync): d_out[M,256] fp32
// ---------------------------------------------------------------------------

#define M_ROWS 100352           // 32*56*56
#define KH     512              // 2*256 split-K fp16

__device__ float  g_qkv[100352ULL * 768];
__device__ __half g_xcat[100352ULL * 512];
__device__ __half g_acat[100352ULL * 512];
__device__ __half g_wq[768ULL * 512];
__device__ __half g_wp[256ULL * 512];

// ======================= helpers ============================================
__device__ __forceinline__ uint32_t smem_u32(const void* p) {
    uint32_t a;
    asm("{ .reg .u64 t; cvta.to.shared.u64 t, %1; cvt.u32.u64 %0, t; }"
        : "=r"(a) : "l"(p));
    return a;
}
__device__ __forceinline__ void cp16(uint32_t s, const void* g) {
    asm volatile("cp.async.cg.shared.global [%0], [%1], 16;"
                 :: "r"(s), "l"(g) : "memory");
}
#define CP_COMMIT() asm volatile("cp.async.commit_group;" ::: "memory")
#define CP_WAIT1()  asm volatile("cp.async.wait_group 1;" ::: "memory")

__device__ __forceinline__ void ldsm4(uint32_t& r0, uint32_t& r1,
                                      uint32_t& r2, uint32_t& r3, uint32_t a) {
    asm volatile("ldmatrix.sync.aligned.m8n8.x4.shared.b16 {%0,%1,%2,%3}, [%4];"
                 : "=r"(r0), "=r"(r1), "=r"(r2), "=r"(r3) : "r"(a));
}
__device__ __forceinline__ void mma16816(float* c, const uint32_t* a,
                                         const uint32_t* b) {
    asm volatile(
        "mma.sync.aligned.m16n8k16.row.col.f32.f16.f16.f32 "
        "{%0,%1,%2,%3}, {%4,%5,%6,%7}, {%8,%9}, {%0,%1,%2,%3};"
        : "+f"(c[0]), "+f"(c[1]), "+f"(c[2]), "+f"(c[3])
        : "r"(a[0]), "r"(a[1]), "r"(a[2]), "r"(a[3]), "r"(b[0]), "r"(b[1]));
}

// ---- packed f32x2 (attention) ----------------------------------------------
__device__ __forceinline__ unsigned long long pk2(float x) {
    unsigned long long r; unsigned u = __float_as_uint(x);
    asm("mov.b64 %0, {%1, %1};" : "=l"(r) : "r"(u));
    return r;
}
__device__ __forceinline__ void ffma2(unsigned long long& d,
                                      unsigned long long a, unsigned long long b) {
    asm("fma.rn.f32x2 %0, %1, %2, %0;" : "+l"(d) : "l"(a), "l"(b));
}
__device__ __forceinline__ float lo32(unsigned long long v) {
    return __uint_as_float((unsigned)v);
}
__device__ __forceinline__ float hi32(unsigned long long v) {
    return __uint_as_float((unsigned)(v >> 32));
}

// ======================= split-fp16 conversion ==============================
// in: [nrows,256] fp32 -> out: [nrows,512] fp16. dupHi: [hi|hi] else [hi|lo].
__global__ void __launch_bounds__(256)
convert_split(const float* __restrict__ in, __half* __restrict__ out,
              int nrows, int dupHi) {
    int t = blockIdx.x * 256 + threadIdx.x;
    if (t >= nrows * 64) return;
    int m = t >> 6;
    int c = (t & 63) << 2;
    float4 v = *(const float4*)(in + (size_t)m * 256 + c);

    __half hx = __float2half_rn(v.x), hy = __float2half_rn(v.y);
    __half hz = __float2half_rn(v.z), hw = __float2half_rn(v.w);
    __half lx, ly, lz, lw;
    if (dupHi) { lx = hx; ly = hy; lz = hz; lw = hw; }
    else {
        lx = __float2half_rn(v.x - __half2float(hx));
        ly = __float2half_rn(v.y - __half2float(hy));
        lz = __float2half_rn(v.z - __half2float(hz));
        lw = __float2half_rn(v.w - __half2float(hw));
    }
    __half* base = out + (size_t)m * KH + c;
    *(__half2*)(base)       = __halves2half2(hx, hy);
    *(__half2*)(base + 2)   = __halves2half2(hz, hw);
    *(__half2*)(base + 256) = __halves2half2(lx, ly);
    *(__half2*)(base + 258) = __halves2half2(lz, lw);
}

// ======================= mma.sync GEMM ======================================
// C[M,N] = A[M,KH] @ W[N,KH]^T + bias, fp32 out. CTA 128x128, 8 warps (4x2),
// warp tile 32x64. BK=32 halves, double-buffered cp.async.
// smem rows padded to 40 halves (80B = 5x16B chunks) -> conflict-free ldmatrix.
#define GROW 40

__global__ void __launch_bounds__(256, 2)
gemm_mma(const __half* __restrict__ A, const __half* __restrict__ W,
         const float* __restrict__ bias, float* __restrict__ C, int N) {
    __shared__ __half sA[2][128 * GROW];
    __shared__ __half sB[2][128 * GROW];

    const int tid  = threadIdx.x;
    const int wid  = tid >> 5;
    const int lane = tid & 31;
    const int wm   = wid & 3;          // 4 warps over M
    const int wn   = wid >> 2;         // 2 warps over N
    const size_t m0 = (size_t)blockIdx.y * 128;
    const int    n0 = blockIdx.x * 128;

    float acc[2][8][4];
#pragma unroll
    for (int i = 0; i < 2; i++)
#pragma unroll
        for (int j = 0; j < 8; j++)
#pragma unroll
            for (int k = 0; k < 4; k++) acc[i][j][k] = 0.f;

    // load mapping: id in [0,512): r=id>>2 (0..127), c=id&3 (16B chunk)
    const int r_ = tid >> 2, c_ = tid & 3;
    const __half* gA = A + (m0 + r_) * KH + c_ * 8;
    const __half* gB = W + (size_t)(n0 + r_) * KH + c_ * 8;
    const uint32_t sA0 = smem_u32(&sA[0][0]);
    const uint32_t sB0 = smem_u32(&sB[0][0]);
    const uint32_t stOff = (r_ * 5 + c_) * 16;           // bytes
    const uint32_t stageBytes = 128 * GROW * 2;

#define LOAD_STAGE(buf, k0)                                                  \
    do {                                                                     \
        cp16(sA0 + (buf) * stageBytes + stOff, gA + (k0));                   \
        cp16(sA0 + (buf) * stageBytes + stOff + 64 * 5 * 16,                 \
             gA + (k0) + (size_t)64 * KH);                                   \
        cp16(sB0 + (buf) * stageBytes + stOff, gB + (k0));                   \
        cp16(sB0 + (buf) * stageBytes + stOff + 64 * 5 * 16,                 \
             gB + (k0) + (size_t)64 * KH);                                   \
    } while (0)

    const int NS = KH / 32;   // 16 slabs
    LOAD_STAGE(0, 0);
    CP_COMMIT();

    // ldmatrix address pieces (constant per thread)
    const int aRow = wm * 32 + (lane & 15);
    const int aChk = lane >> 4;                         // 0/1
    const int bRowBase = wn * 64 + (lane & 7) + ((lane >> 4) << 3);
    const int bChk = (lane >> 3) & 1;

    for (int s = 0; s < NS; s++) {
        const int buf = s & 1;
        if (s + 1 < NS) LOAD_STAGE(buf ^ 1, (s + 1) * 32);
        CP_COMMIT();
        CP_WAIT1();
        __syncthreads();

        const uint32_t aBase = sA0 + buf * stageBytes;
        const uint32_t bBase = sB0 + buf * stageBytes;
#pragma unroll
        for (int kk = 0; kk < 2; kk++) {
            uint32_t af[2][4];
#pragma unroll
            for (int mt = 0; mt < 2; mt++) {
                uint32_t ad = aBase +
                    ((aRow + mt * 16) * 5 + kk * 2 + aChk) * 16;
                ldsm4(af[mt][0], af[mt][1], af[mt][2], af[mt][3], ad);
            }
            uint32_t bf[8][2];
#pragma unroll
            for (int pr = 0; pr < 4; pr++) {
                uint32_t bd = bBase +
                    ((bRowBase + pr * 16) * 5 + kk * 2 + bChk) * 16;
                uint32_t r0, r1, r2, r3;
                ldsm4(r0, r1, r2, r3, bd);
                bf[2 * pr][0] = r0; bf[2 * pr][1] = r1;
                bf[2 * pr + 1][0] = r2; bf[2 * pr + 1][1] = r3;
            }
#pragma unroll
            for (int mt = 0; mt < 2; mt++)
#pragma unroll
                for (int nt = 0; nt < 8; nt++)
                    mma16816(acc[mt][nt], af[mt], bf[nt]);
        }
        __syncthreads();
    }

    // ---- epilogue ----
    const int g  = lane >> 2;
    const int t4 = lane & 3;
#pragma unroll
    for (int nt = 0; nt < 8; nt++) {
        const int col = n0 + wn * 64 + nt * 8 + 2 * t4;
        float2 bb = *(const float2*)(bias + col);
#pragma unroll
        for (int mt = 0; mt < 2; mt++) {
            size_t row0 = m0 + wm * 32 + mt * 16 + g;
            float2 v0 = make_float2(acc[mt][nt][0] + bb.x,
                                    acc[mt][nt][1] + bb.y);
            float2 v1 = make_float2(acc[mt][nt][2] + bb.x,
                                    acc[mt][nt][3] + bb.y);
            *(float2*)(C + row0 * N + col)       = v0;
            *(float2*)(C + (row0 + 8) * N + col) = v1;
        }
    }
#undef LOAD_STAGE
}

// ======================= attention ==========================================
__global__ void __launch_bounds__(128)
attn_kernel(const float* __restrict__ qkv, const float* __restrict__ table,
            __half* __restrict__ outp) {
    __shared__ float Qs[49][36];
    __shared__ float Ks[49][36];
    __shared__ float Vs[49][36];
    __shared__ float S[49][50];
    __shared__ float Bs[169];
    __shared__ int   rowi[49];

    const int tid  = threadIdx.x;
    const int blk  = blockIdx.x;
    const int head = blk & 7;
    const int w    = blk >> 3;
    const int b    = w >> 6;
    const int wr   = (w >> 3) & 7;
    const int wc   = w & 7;

    if (tid < 49) {
        int ih = tid / 7, iw = tid - ih * 7;
        int hh = wr * 7 + ih;
        int vv = wc * 7 + iw;
        int oh = hh + 3; if (oh >= 56) oh -= 56;
        int ow = vv + 3; if (ow >= 56) ow -= 56;
        rowi[tid] = (b * 56 + oh) * 56 + ow;
    }
    for (int t = tid; t < 169; t += 128) Bs[t] = table[t * 8 + head];
    __syncthreads();

    for (int idx = tid; idx < 392; idx += 128) {
        int p = idx >> 3, q = idx & 7;
        const float4* src =
            (const float4*)(qkv + (size_t)rowi[p] * 768 + head * 32) + q;
        *(float4*)&Qs[p][q * 4] = src[0];
        *(float4*)&Ks[p][q * 4] = src[64];
        *(float4*)&Vs[p][q * 4] = src[128];
    }
    __syncthreads();

    const float scale = 0.17677669529663687f;

    if (tid < 98) {
        int i = tid >> 1;
        int jbeg = (tid & 1) * 25;
        int jend = (tid & 1) ? 49 : 25;
        unsigned long long q2[16];
        const unsigned long long* qp = (const unsigned long long*)&Qs[i][0];
#pragma unroll
        for (int z = 0; z < 16; z++) q2[z] = qp[z];

        int ih = i / 7, iw = i - ih * 7;
        int hi_ = wr * 7 + ih, wi_ = wc * 7 + iw;
        int rhi = (hi_ < 49) ? 0 : (hi_ < 53 ? 1 : 2);
        int rwi = (wi_ < 49) ? 0 : (wi_ < 53 ? 1 : 2);

        for (int j = jbeg; j < jend; j++) {
            const unsigned long long* kp = (const unsigned long long*)&Ks[j][0];
            unsigned long long a = 0ULL;
#pragma unroll
            for (int z = 0; z < 16; z++) ffma2(a, q2[z], kp[z]);
            float s = (lo32(a) + hi32(a)) * scale;

            int jh = j / 7, jw = j - jh * 7;
            s += Bs[(ih - jh + 6) * 13 + (iw - jw + 6)];

            int hj = wr * 7 + jh, wj = wc * 7 + jw;
            int rhj = (hj < 49) ? 0 : (hj < 53 ? 1 : 2);
            int rwj = (wj < 49) ? 0 : (wj < 53 ? 1 : 2);
            if ((rhi != rhj) | (rwi != rwj)) s -= 100.0f;
            S[i][j] = s;
        }
    }
    __syncthreads();

    if (tid < 49) {
        float m = -1e30f;
#pragma unroll 7
        for (int j = 0; j < 49; j++) m = fmaxf(m, S[tid][j]);
        float sum = 0.f;
#pragma unroll 7
        for (int j = 0; j < 49; j++) {
            float e = __expf(S[tid][j] - m);
            S[tid][j] = e;
            sum += e;
        }
        float inv = 1.0f / sum;
#pragma unroll 7
        for (int j = 0; j < 49; j++) S[tid][j] *= inv;
    }
    __syncthreads();

    if (tid < 98) {
        int i  = tid >> 1;
        int dh = (tid & 1) * 16;
        unsigned long long o2[8];
#pragma unroll
        for (int z = 0; z < 8; z++) o2[z] = 0ULL;
        for (int j = 0; j < 49; j++) {
            unsigned long long ss = pk2(S[i][j]);
            const unsigned long long* vp = (const unsigned long long*)&Vs[j][dh];
#pragma unroll
            for (int z = 0; z < 8; z++) ffma2(o2[z], ss, vp[z]);
        }
        // write split-fp16 [hi | lo] directly
        __half* dst = outp + (size_t)rowi[i] * KH + head * 32 + dh;
#pragma unroll
        for (int z = 0; z < 8; z++) {
            float a = lo32(o2[z]), bv = hi32(o2[z]);
            __half ha = __float2half_rn(a);
            __half hb = __float2half_rn(bv);
            __half la = __float2half_rn(a - __half2float(ha));
            __half lb = __float2half_rn(bv - __half2float(hb));
            *(__half2*)(dst + 2 * z)       = __halves2half2(ha, hb);
            *(__half2*)(dst + 256 + 2 * z) = __halves2half2(la, lb);
        }
    }
}

// ---------------------------------------------------------------------------
extern "C" void kernel_launch(void* const* d_in, const int* in_sizes, int n_in,
                              void* d_out, int out_size) {
    const float* x      = (const float*)d_in[0];
    const float* qkv_w  = (const float*)d_in[1];
    const float* qkv_b  = (const float*)d_in[2];
    const float* proj_w = (const float*)d_in[3];
    const float* proj_b = (const float*)d_in[4];
    const float* table  = (const float*)d_in[5];
    float* out = (float*)d_out;

    void *qkv_p, *xcat_p, *acat_p, *wq_p, *wp_p;
    cudaGetSymbolAddress(&qkv_p,  g_qkv);
    cudaGetSymbolAddress(&xcat_p, g_xcat);
    cudaGetSymbolAddress(&acat_p, g_acat);
    cudaGetSymbolAddress(&wq_p,   g_wq);
    cudaGetSymbolAddress(&wp_p,   g_wp);
    float*  qkv  = (float*)qkv_p;
    __half* xcat = (__half*)xcat_p;
    __half* acat = (__half*)acat_p;
    __half* wq   = (__half*)wq_p;
    __half* wp   = (__half*)wp_p;

    // conversions to split-fp16
    convert_split<<<(M_ROWS * 64 + 255) / 256, 256>>>(x, xcat, M_ROWS, 0);
    convert_split<<<(768 * 64 + 255) / 256, 256>>>(qkv_w, wq, 768, 1);
    convert_split<<<(256 * 64 + 255) / 256, 256>>>(proj_w, wp, 256, 1);

    // QKV: M=100352, N=768
    dim3 gq(768 / 128, M_ROWS / 128);
    gemm_mma<<<gq, 256>>>(xcat, wq, qkv_b, qkv, 768);

    // attention
    attn_kernel<<<2048 * 8, 128>>>(qkv, table, acat);

    // proj: M=100352, N=256
    dim3 gp(256 / 128, M_ROWS / 128);
    gemm_mma<<<gp, 256>>>(acat, wp, proj_b, out, 256);
}

// round 5
// speedup vs baseline: 2.9444x; 1.5086x over previous
#include <cuda_runtime.h>
#include <cuda_fp16.h>
#include <cstdint>

// ---------------------------------------------------------------------------
// Swin shifted-window attention, B=32 H=W=56 C=256, 7x7 win, shift 3, 8 heads.
//
//  1) convert x -> x_cat fp16 [M,512] = [hi | lo]      (2-term K-split)
//     convert w -> w_cat fp16 [N,512] = [hi | hi]
//  2) QKV GEMM (mma.sync f16, fp32 acc) -> g_qkv fp16 [M,768]
//  3) windowed attention: per-(window,head) tensor-core MMA (49 padded to 64),
//     fused bias+mask+softmax on fragments, writes acat fp16 [M,512] split
//  4) proj GEMM (mma.sync): d_out[M,256] fp32
// ---------------------------------------------------------------------------

#define M_ROWS 100352           // 32*56*56
#define KH     512              // 2*256 split-K fp16

__device__ __half g_qkv[100352ULL * 768];
__device__ __half g_xcat[100352ULL * 512];
__device__ __half g_acat[100352ULL * 512];
__device__ __half g_wq[768ULL * 512];
__device__ __half g_wp[256ULL * 512];

// ======================= helpers ============================================
__device__ __forceinline__ uint32_t smem_u32(const void* p) {
    uint32_t a;
    asm("{ .reg .u64 t; cvta.to.shared.u64 t, %1; cvt.u32.u64 %0, t; }"
        : "=r"(a) : "l"(p));
    return a;
}
__device__ __forceinline__ uint32_t h2u(__half2 h) {
    union { __half2 h; uint32_t u; } c;
    c.h = h;
    return c.u;
}
__device__ __forceinline__ void cp16(uint32_t s, const void* g) {
    asm volatile("cp.async.cg.shared.global [%0], [%1], 16;"
                 :: "r"(s), "l"(g) : "memory");
}
#define CP_COMMIT() asm volatile("cp.async.commit_group;" ::: "memory")
#define CP_WAIT1()  asm volatile("cp.async.wait_group 1;" ::: "memory")

__device__ __forceinline__ void ldsm4(uint32_t& r0, uint32_t& r1,
                                      uint32_t& r2, uint32_t& r3, uint32_t a) {
    asm volatile("ldmatrix.sync.aligned.m8n8.x4.shared.b16 {%0,%1,%2,%3}, [%4];"
                 : "=r"(r0), "=r"(r1), "=r"(r2), "=r"(r3) : "r"(a));
}
__device__ __forceinline__ void ldsm4t(uint32_t& r0, uint32_t& r1,
                                       uint32_t& r2, uint32_t& r3, uint32_t a) {
    asm volatile(
        "ldmatrix.sync.aligned.m8n8.x4.trans.shared.b16 {%0,%1,%2,%3}, [%4];"
        : "=r"(r0), "=r"(r1), "=r"(r2), "=r"(r3) : "r"(a));
}
__device__ __forceinline__ void mma16816(float* c, const uint32_t* a,
                                         const uint32_t* b) {
    asm volatile(
        "mma.sync.aligned.m16n8k16.row.col.f32.f16.f16.f32 "
        "{%0,%1,%2,%3}, {%4,%5,%6,%7}, {%8,%9}, {%0,%1,%2,%3};"
        : "+f"(c[0]), "+f"(c[1]), "+f"(c[2]), "+f"(c[3])
        : "r"(a[0]), "r"(a[1]), "r"(a[2]), "r"(a[3]), "r"(b[0]), "r"(b[1]));
}

// ======================= split-fp16 conversion ==============================
__global__ void __launch_bounds__(256)
convert_split(const float* __restrict__ in, __half* __restrict__ out,
              int nrows, int dupHi) {
    int t = blockIdx.x * 256 + threadIdx.x;
    if (t >= nrows * 64) return;
    int m = t >> 6;
    int c = (t & 63) << 2;
    float4 v = *(const float4*)(in + (size_t)m * 256 + c);

    __half hx = __float2half_rn(v.x), hy = __float2half_rn(v.y);
    __half hz = __float2half_rn(v.z), hw = __float2half_rn(v.w);
    __half lx, ly, lz, lw;
    if (dupHi) { lx = hx; ly = hy; lz = hz; lw = hw; }
    else {
        lx = __float2half_rn(v.x - __half2float(hx));
        ly = __float2half_rn(v.y - __half2float(hy));
        lz = __float2half_rn(v.z - __half2float(hz));
        lw = __float2half_rn(v.w - __half2float(hw));
    }
    __half* base = out + (size_t)m * KH + c;
    *(__half2*)(base)       = __halves2half2(hx, hy);
    *(__half2*)(base + 2)   = __halves2half2(hz, hw);
    *(__half2*)(base + 256) = __halves2half2(lx, ly);
    *(__half2*)(base + 258) = __halves2half2(lz, lw);
}

// ======================= mma.sync GEMM ======================================
// C[M,N] = A[M,KH] @ W[N,KH]^T + bias. CTA 128x128, 8 warps (4x2),
// warp tile 32x64, BK=32, double-buffered cp.async. OT = float or __half.
#define GROW 40

template <typename OT>
__global__ void __launch_bounds__(256, 2)
gemm_mma(const __half* __restrict__ A, const __half* __restrict__ W,
         const float* __restrict__ bias, OT* __restrict__ C, int N) {
    __shared__ __half sA[2][128 * GROW];
    __shared__ __half sB[2][128 * GROW];

    const int tid  = threadIdx.x;
    const int wid  = tid >> 5;
    const int lane = tid & 31;
    const int wm   = wid & 3;
    const int wn   = wid >> 2;
    const size_t m0 = (size_t)blockIdx.y * 128;
    const int    n0 = blockIdx.x * 128;

    float acc[2][8][4];
#pragma unroll
    for (int i = 0; i < 2; i++)
#pragma unroll
        for (int j = 0; j < 8; j++)
#pragma unroll
            for (int k = 0; k < 4; k++) acc[i][j][k] = 0.f;

    const int r_ = tid >> 2, c_ = tid & 3;
    const __half* gA = A + (m0 + r_) * KH + c_ * 8;
    const __half* gB = W + (size_t)(n0 + r_) * KH + c_ * 8;
    const uint32_t sA0 = smem_u32(&sA[0][0]);
    const uint32_t sB0 = smem_u32(&sB[0][0]);
    const uint32_t stOff = (r_ * 5 + c_) * 16;
    const uint32_t stageBytes = 128 * GROW * 2;

#define LOAD_STAGE(buf, k0)                                                  \
    do {                                                                     \
        cp16(sA0 + (buf) * stageBytes + stOff, gA + (k0));                   \
        cp16(sA0 + (buf) * stageBytes + stOff + 64 * 5 * 16,                 \
             gA + (k0) + (size_t)64 * KH);                                   \
        cp16(sB0 + (buf) * stageBytes + stOff, gB + (k0));                   \
        cp16(sB0 + (buf) * stageBytes + stOff + 64 * 5 * 16,                 \
             gB + (k0) + (size_t)64 * KH);                                   \
    } while (0)

    const int NS = KH / 32;
    LOAD_STAGE(0, 0);
    CP_COMMIT();

    const int aRow = wm * 32 + (lane & 15);
    const int aChk = lane >> 4;
    const int bRowBase = wn * 64 + (lane & 7) + ((lane >> 4) << 3);
    const int bChk = (lane >> 3) & 1;

    for (int s = 0; s < NS; s++) {
        const int buf = s & 1;
        if (s + 1 < NS) LOAD_STAGE(buf ^ 1, (s + 1) * 32);
        CP_COMMIT();
        CP_WAIT1();
        __syncthreads();

        const uint32_t aBase = sA0 + buf * stageBytes;
        const uint32_t bBase = sB0 + buf * stageBytes;
#pragma unroll
        for (int kk = 0; kk < 2; kk++) {
            uint32_t af[2][4];
#pragma unroll
            for (int mt = 0; mt < 2; mt++) {
                uint32_t ad = aBase +
                    ((aRow + mt * 16) * 5 + kk * 2 + aChk) * 16;
                ldsm4(af[mt][0], af[mt][1], af[mt][2], af[mt][3], ad);
            }
            uint32_t bf[8][2];
#pragma unroll
            for (int pr = 0; pr < 4; pr++) {
                uint32_t bd = bBase +
                    ((bRowBase + pr * 16) * 5 + kk * 2 + bChk) * 16;
                uint32_t r0, r1, r2, r3;
                ldsm4(r0, r1, r2, r3, bd);
                bf[2 * pr][0] = r0; bf[2 * pr][1] = r1;
                bf[2 * pr + 1][0] = r2; bf[2 * pr + 1][1] = r3;
            }
#pragma unroll
            for (int mt = 0; mt < 2; mt++)
#pragma unroll
                for (int nt = 0; nt < 8; nt++)
                    mma16816(acc[mt][nt], af[mt], bf[nt]);
        }
        __syncthreads();
    }

    const int g  = lane >> 2;
    const int t4 = lane & 3;
#pragma unroll
    for (int nt = 0; nt < 8; nt++) {
        const int col = n0 + wn * 64 + nt * 8 + 2 * t4;
        float2 bb = *(const float2*)(bias + col);
#pragma unroll
        for (int mt = 0; mt < 2; mt++) {
            size_t row0 = m0 + wm * 32 + mt * 16 + g;
            float v00 = acc[mt][nt][0] + bb.x, v01 = acc[mt][nt][1] + bb.y;
            float v10 = acc[mt][nt][2] + bb.x, v11 = acc[mt][nt][3] + bb.y;
            if constexpr (sizeof(OT) == 4) {
                *(float2*)((float*)C + row0 * N + col) = make_float2(v00, v01);
                *(float2*)((float*)C + (row0 + 8) * N + col) = make_float2(v10, v11);
            } else {
                *(__half2*)((__half*)C + row0 * N + col) =
                    __floats2half2_rn(v00, v01);
                *(__half2*)((__half*)C + (row0 + 8) * N + col) =
                    __floats2half2_rn(v10, v11);
            }
        }
    }
#undef LOAD_STAGE
}

// ======================= tensor-core attention ==============================
// Block = (window, head), 64 threads (2 warps). 49 tokens padded to 64.
// S = Q K^T (mma), fused scale+bias+mask+softmax on fragments, O = P V (mma).
__global__ void __launch_bounds__(64)
attn_mma(const __half* __restrict__ qkv, const float* __restrict__ table,
         __half* __restrict__ outp) {
    __shared__ __align__(16) __half Qs[64 * 40];
    __shared__ __align__(16) __half Ks[64 * 40];
    __shared__ __align__(16) __half Vs[64 * 40];
    __shared__ float Bs[169];
    __shared__ int   rowi[49];
    __shared__ int   cinfo[64];

    const int tid  = threadIdx.x;
    const int w    = tid >> 5;
    const int lane = tid & 31;
    const int head = blockIdx.x & 7;
    const int win  = blockIdx.x >> 3;
    const int b    = win >> 6;
    const int wr   = (win >> 3) & 7;
    const int wc   = win & 7;

    if (tid < 49) {
        int ih = tid / 7, iw = tid - ih * 7;
        int oh = wr * 7 + ih + 3; if (oh >= 56) oh -= 56;
        int ow = wc * 7 + iw + 3; if (ow >= 56) ow -= 56;
        rowi[tid] = (b * 56 + oh) * 56 + ow;
    }
    {   // column info (all 64, invalid flag for >=49)
        int j = tid;
        int jh = j / 7, jw = j - jh * 7;
        int hj = wr * 7 + jh, wj = wc * 7 + jw;
        int rj = ((hj < 49) ? 0 : (hj < 53 ? 1 : 2)) * 3 +
                 ((wj < 49) ? 0 : (wj < 53 ? 1 : 2));
        cinfo[j] = (jh * 13 + jw) | (rj << 8) | ((j < 49 ? 0 : 1) << 15);
    }
    for (int t = tid; t < 169; t += 64) Bs[t] = table[t * 8 + head];
    // zero pad rows 49..63 of Q,K,V (15 rows x 64B each, 3 mats = 180 uint4)
    for (int idx = tid; idx < 180; idx += 64) {
        int mat = idx / 60, rem = idx - mat * 60;
        int r = 49 + (rem >> 2), q = rem & 3;
        __half* base = (mat == 0) ? Qs : (mat == 1) ? Ks : Vs;
        *(uint4*)(base + r * 40 + q * 8) = make_uint4(0, 0, 0, 0);
    }
    __syncthreads();

    // gather Q,K,V rows (49 x 32 halves each)
    for (int idx = tid; idx < 196; idx += 64) {
        int p = idx >> 2, q = idx & 3;
        const __half* src = qkv + (size_t)rowi[p] * 768 + head * 32 + q * 8;
        *(uint4*)(Qs + p * 40 + q * 8) = *(const uint4*)(src);
        *(uint4*)(Ks + p * 40 + q * 8) = *(const uint4*)(src + 256);
        *(uint4*)(Vs + p * 40 + q * 8) = *(const uint4*)(src + 512);
    }
    __syncthreads();

    const uint32_t sQ = smem_u32(Qs), sK = smem_u32(Ks), sV = smem_u32(Vs);

    // ---- S = Q K^T ----
    uint32_t aQ[2][2][4];
#pragma unroll
    for (int mt = 0; mt < 2; mt++)
#pragma unroll
        for (int kk = 0; kk < 2; kk++) {
            int row = w * 32 + mt * 16 + (lane & 15);
            uint32_t ad = sQ + row * 80 + (kk * 2 + (lane >> 4)) * 16;
            ldsm4(aQ[mt][kk][0], aQ[mt][kk][1], aQ[mt][kk][2], aQ[mt][kk][3], ad);
        }
    uint32_t bK[2][8][2];
#pragma unroll
    for (int kk = 0; kk < 2; kk++)
#pragma unroll
        for (int pr = 0; pr < 4; pr++) {
            int row = pr * 16 + (lane & 7) + ((lane >> 4) << 3);
            uint32_t ad = sK + row * 80 + (kk * 2 + ((lane >> 3) & 1)) * 16;
            uint32_t r0, r1, r2, r3;
            ldsm4(r0, r1, r2, r3, ad);
            bK[kk][2 * pr][0] = r0;     bK[kk][2 * pr][1] = r1;
            bK[kk][2 * pr + 1][0] = r2; bK[kk][2 * pr + 1][1] = r3;
        }
    float s[2][8][4];
#pragma unroll
    for (int mt = 0; mt < 2; mt++)
#pragma unroll
        for (int nt = 0; nt < 8; nt++) {
            s[mt][nt][0] = s[mt][nt][1] = s[mt][nt][2] = s[mt][nt][3] = 0.f;
            mma16816(s[mt][nt], aQ[mt][0], bK[0][nt]);
            mma16816(s[mt][nt], aQ[mt][1], bK[1][nt]);
        }

    // ---- logits: scale + bias + shift-mask ----
    const int g  = lane >> 2;
    const int t4 = lane & 3;
    const float scale = 0.17677669529663687f;   // 1/sqrt(32)

    int cp[16];
#pragma unroll
    for (int nt = 0; nt < 8; nt++) {
        cp[2 * nt]     = cinfo[nt * 8 + 2 * t4];
        cp[2 * nt + 1] = cinfo[nt * 8 + 2 * t4 + 1];
    }
    int   rb[2][2], ri[2][2];
    bool  rv[2][2];
#pragma unroll
    for (int mt = 0; mt < 2; mt++)
#pragma unroll
        for (int h = 0; h < 2; h++) {
            int i = w * 32 + mt * 16 + g + 8 * h;
            rv[mt][h] = (i < 49);
            int ih = i / 7, iw = i - ih * 7;
            if (!rv[mt][h]) { ih = 0; iw = 0; }
            rb[mt][h] = (ih + 6) * 13 + iw + 6;
            int hh = wr * 7 + ih, vv = wc * 7 + iw;
            ri[mt][h] = ((hh < 49) ? 0 : (hh < 53 ? 1 : 2)) * 3 +
                        ((vv < 49) ? 0 : (vv < 53 ? 1 : 2));
        }
#pragma unroll
    for (int mt = 0; mt < 2; mt++)
#pragma unroll
        for (int nt = 0; nt < 8; nt++)
#pragma unroll
            for (int e = 0; e < 4; e++) {
                int h = e >> 1, cs = e & 1;
                float v;
                if (!rv[mt][h]) v = 0.f;
                else {
                    int ci = cp[2 * nt + cs];
                    if (ci >> 15) v = -1e4f;
                    else {
                        v = s[mt][nt][e] * scale + Bs[rb[mt][h] - (ci & 0xFF)];
                        if (((ci >> 8) & 0xF) != ri[mt][h]) v -= 100.f;
                    }
                }
                s[mt][nt][e] = v;
            }

    // ---- softmax ----
    float zinv[2][2];
#pragma unroll
    for (int mt = 0; mt < 2; mt++)
#pragma unroll
        for (int h = 0; h < 2; h++) {
            float m = -1e30f;
#pragma unroll
            for (int nt = 0; nt < 8; nt++) {
                m = fmaxf(m, s[mt][nt][2 * h]);
                m = fmaxf(m, s[mt][nt][2 * h + 1]);
            }
            m = fmaxf(m, __shfl_xor_sync(0xffffffffu, m, 1));
            m = fmaxf(m, __shfl_xor_sync(0xffffffffu, m, 2));
            float sum = 0.f;
#pragma unroll
            for (int nt = 0; nt < 8; nt++) {
                float e0 = __expf(s[mt][nt][2 * h] - m);
                float e1 = __expf(s[mt][nt][2 * h + 1] - m);
                s[mt][nt][2 * h] = e0;
                s[mt][nt][2 * h + 1] = e1;
                sum += e0 + e1;
            }
            sum += __shfl_xor_sync(0xffffffffu, sum, 1);
            sum += __shfl_xor_sync(0xffffffffu, sum, 2);
            zinv[mt][h] = 1.0f / sum;
        }

    // ---- P fragments (fp16) ----
    uint32_t aP[2][4][4];
#pragma unroll
    for (int mt = 0; mt < 2; mt++)
#pragma unroll
        for (int kt = 0; kt < 4; kt++) {
            aP[mt][kt][0] = h2u(__floats2half2_rn(s[mt][2 * kt][0],
                                                  s[mt][2 * kt][1]));
            aP[mt][kt][1] = h2u(__floats2half2_rn(s[mt][2 * kt][2],
                                                  s[mt][2 * kt][3]));
            aP[mt][kt][2] = h2u(__floats2half2_rn(s[mt][2 * kt + 1][0],
                                                  s[mt][2 * kt + 1][1]));
            aP[mt][kt][3] = h2u(__floats2half2_rn(s[mt][2 * kt + 1][2],
                                                  s[mt][2 * kt + 1][3]));
        }

    // ---- V fragments (trans ldmatrix) ----
    uint32_t bV[4][4][2];
#pragma unroll
    for (int kt = 0; kt < 4; kt++)
#pragma unroll
        for (int nh = 0; nh < 2; nh++) {
            int row = kt * 16 + (lane & 7) + (((lane >> 3) & 1) << 3);
            uint32_t ad = sV + row * 80 + nh * 32 + ((lane >> 4) << 4);
            uint32_t r0, r1, r2, r3;
            ldsm4t(r0, r1, r2, r3, ad);
            bV[kt][2 * nh][0] = r0;     bV[kt][2 * nh][1] = r1;
            bV[kt][2 * nh + 1][0] = r2; bV[kt][2 * nh + 1][1] = r3;
        }

    // ---- O = P V ----
    float o[2][4][4];
#pragma unroll
    for (int mt = 0; mt < 2; mt++)
#pragma unroll
        for (int vn = 0; vn < 4; vn++) {
            o[mt][vn][0] = o[mt][vn][1] = o[mt][vn][2] = o[mt][vn][3] = 0.f;
#pragma unroll
            for (int kt = 0; kt < 4; kt++)
                mma16816(o[mt][vn], aP[mt][kt], bV[kt][vn]);
        }

    // ---- epilogue: normalize, split hi/lo fp16, scatter ----
#pragma unroll
    for (int mt = 0; mt < 2; mt++)
#pragma unroll
        for (int h = 0; h < 2; h++) {
            int i = w * 32 + mt * 16 + g + 8 * h;
            if (i >= 49) continue;
            float rz = zinv[mt][h];
            __half* dst = outp + (size_t)rowi[i] * KH + head * 32;
#pragma unroll
            for (int vn = 0; vn < 4; vn++) {
                int col = vn * 8 + 2 * t4;
                float v0 = o[mt][vn][2 * h] * rz;
                float v1 = o[mt][vn][2 * h + 1] * rz;
                __half h0 = __float2half_rn(v0), h1 = __float2half_rn(v1);
                __half l0 = __float2half_rn(v0 - __half2float(h0));
                __half l1 = __float2half_rn(v1 - __half2float(h1));
                *(__half2*)(dst + col)       = __halves2half2(h0, h1);
                *(__half2*)(dst + 256 + col) = __halves2half2(l0, l1);
            }
        }
}

// ---------------------------------------------------------------------------
extern "C" void kernel_launch(void* const* d_in, const int* in_sizes, int n_in,
                              void* d_out, int out_size) {
    const float* x      = (const float*)d_in[0];
    const float* qkv_w  = (const float*)d_in[1];
    const float* qkv_b  = (const float*)d_in[2];
    const float* proj_w = (const float*)d_in[3];
    const float* proj_b = (const float*)d_in[4];
    const float* table  = (const float*)d_in[5];
    float* out = (float*)d_out;

    void *qkv_p, *xcat_p, *acat_p, *wq_p, *wp_p;
    cudaGetSymbolAddress(&qkv_p,  g_qkv);
    cudaGetSymbolAddress(&xcat_p, g_xcat);
    cudaGetSymbolAddress(&acat_p, g_acat);
    cudaGetSymbolAddress(&wq_p,   g_wq);
    cudaGetSymbolAddress(&wp_p,   g_wp);
    __half* qkv  = (__half*)qkv_p;
    __half* xcat = (__half*)xcat_p;
    __half* acat = (__half*)acat_p;
    __half* wq   = (__half*)wq_p;
    __half* wp   = (__half*)wp_p;

    convert_split<<<(M_ROWS * 64 + 255) / 256, 256>>>(x, xcat, M_ROWS, 0);
    convert_split<<<(768 * 64 + 255) / 256, 256>>>(qkv_w, wq, 768, 1);
    convert_split<<<(256 * 64 + 255) / 256, 256>>>(proj_w, wp, 256, 1);

    dim3 gq(768 / 128, M_ROWS / 128);
    gemm_mma<__half><<<gq, 256>>>(xcat, wq, qkv_b, qkv, 768);

    attn_mma<<<2048 * 8, 64>>>(qkv, table, acat);

    dim3 gp(256 / 128, M_ROWS / 128);
    gemm_mma<float><<<gp, 256>>>(acat, wp, proj_b, out, 256);
}

// round 6
// speedup vs baseline: 3.1305x; 1.0632x over previous
#include <cuda_runtime.h>
#include <cuda_fp16.h>
#include <cstdint>

// ---------------------------------------------------------------------------
// Swin shifted-window attention, B=32 H=W=56 C=256, 7x7 win, shift 3, 8 heads.
//
//  1) convert x -> x_cat fp16 [M,512] = [hi | lo]      (2-term K-split)
//     convert w -> w_cat fp16 [N,512] = [hi | hi]
//  2) QKV GEMM (mma.sync f16, fp32 acc, 4-stage cp.async) -> g_qkv fp16 [M,768]
//  3) windowed attention: per-(window,head) tensor-core MMA (49 padded to 64),
//     fused bias+mask+softmax on fragments, writes acat fp16 [M,512] split
//  4) proj GEMM: d_out[M,256] fp32
// ---------------------------------------------------------------------------

#define M_ROWS 100352           // 32*56*56
#define KH     512              // 2*256 split-K fp16

__device__ __half g_qkv[100352ULL * 768];
__device__ __half g_xcat[100352ULL * 512];
__device__ __half g_acat[100352ULL * 512];
__device__ __half g_wq[768ULL * 512];
__device__ __half g_wp[256ULL * 512];

// ======================= helpers ============================================
__device__ __forceinline__ uint32_t smem_u32(const void* p) {
    uint32_t a;
    asm("{ .reg .u64 t; cvta.to.shared.u64 t, %1; cvt.u32.u64 %0, t; }"
        : "=r"(a) : "l"(p));
    return a;
}
__device__ __forceinline__ uint32_t h2u(__half2 h) {
    union { __half2 h; uint32_t u; } c;
    c.h = h;
    return c.u;
}
__device__ __forceinline__ void cp16(uint32_t s, const void* g) {
    asm volatile("cp.async.cg.shared.global [%0], [%1], 16;"
                 :: "r"(s), "l"(g) : "memory");
}
#define CP_COMMIT() asm volatile("cp.async.commit_group;" ::: "memory")
#define CP_WAIT2()  asm volatile("cp.async.wait_group 2;" ::: "memory")

__device__ __forceinline__ void ldsm4(uint32_t& r0, uint32_t& r1,
                                      uint32_t& r2, uint32_t& r3, uint32_t a) {
    asm volatile("ldmatrix.sync.aligned.m8n8.x4.shared.b16 {%0,%1,%2,%3}, [%4];"
                 : "=r"(r0), "=r"(r1), "=r"(r2), "=r"(r3) : "r"(a));
}
__device__ __forceinline__ void ldsm4t(uint32_t& r0, uint32_t& r1,
                                       uint32_t& r2, uint32_t& r3, uint32_t a) {
    asm volatile(
        "ldmatrix.sync.aligned.m8n8.x4.trans.shared.b16 {%0,%1,%2,%3}, [%4];"
        : "=r"(r0), "=r"(r1), "=r"(r2), "=r"(r3) : "r"(a));
}
__device__ __forceinline__ void mma16816(float* c, const uint32_t* a,
                                         const uint32_t* b) {
    asm volatile(
        "mma.sync.aligned.m16n8k16.row.col.f32.f16.f16.f32 "
        "{%0,%1,%2,%3}, {%4,%5,%6,%7}, {%8,%9}, {%0,%1,%2,%3};"
        : "+f"(c[0]), "+f"(c[1]), "+f"(c[2]), "+f"(c[3])
        : "r"(a[0]), "r"(a[1]), "r"(a[2]), "r"(a[3]), "r"(b[0]), "r"(b[1]));
}

// ======================= split-fp16 conversion ==============================
__global__ void __launch_bounds__(256)
convert_split(const float* __restrict__ in, __half* __restrict__ out,
              int nrows, int dupHi) {
    int t = blockIdx.x * 256 + threadIdx.x;
    if (t >= nrows * 64) return;
    int m = t >> 6;
    int c = (t & 63) << 2;
    float4 v = *(const float4*)(in + (size_t)m * 256 + c);

    __half hx = __float2half_rn(v.x), hy = __float2half_rn(v.y);
    __half hz = __float2half_rn(v.z), hw = __float2half_rn(v.w);
    __half lx, ly, lz, lw;
    if (dupHi) { lx = hx; ly = hy; lz = hz; lw = hw; }
    else {
        lx = __float2half_rn(v.x - __half2float(hx));
        ly = __float2half_rn(v.y - __half2float(hy));
        lz = __float2half_rn(v.z - __half2float(hz));
        lw = __float2half_rn(v.w - __half2float(hw));
    }
    __half* base = out + (size_t)m * KH + c;
    *(__half2*)(base)       = __halves2half2(hx, hy);
    *(__half2*)(base + 2)   = __halves2half2(hz, hw);
    *(__half2*)(base + 256) = __halves2half2(lx, ly);
    *(__half2*)(base + 258) = __halves2half2(lz, lw);
}

// ======================= mma.sync GEMM (4-stage pipeline) ====================
// C[M,N] = A[M,KH] @ W[N,KH]^T + bias. CTA 128x128, 8 warps (4x2),
// warp tile 32x64, BK=32, 4-stage cp.async circular buffer,
// ONE __syncthreads per slab. Dynamic smem 80KB.
#define GROW   40
#define ASZ    (128 * GROW * 2)       // 10240 B per stage per matrix
#define STAGEB (2 * ASZ)              // 20480 B per stage
#define NSTG   4
#define GEMM_SMEM (NSTG * STAGEB)     // 81920 B

template <typename OT>
__global__ void __launch_bounds__(256, 2)
gemm_mma(const __half* __restrict__ A, const __half* __restrict__ W,
         const float* __restrict__ bias, OT* __restrict__ C, int N) {
    extern __shared__ __half smbuf[];

    const int tid  = threadIdx.x;
    const int wid  = tid >> 5;
    const int lane = tid & 31;
    const int wm   = wid & 3;
    const int wn   = wid >> 2;
    const size_t m0 = (size_t)blockIdx.y * 128;
    const int    n0 = blockIdx.x * 128;

    float acc[2][8][4];
#pragma unroll
    for (int i = 0; i < 2; i++)
#pragma unroll
        for (int j = 0; j < 8; j++)
#pragma unroll
            for (int k = 0; k < 4; k++) acc[i][j][k] = 0.f;

    const int r_ = tid >> 2, c_ = tid & 3;
    const __half* gA = A + (m0 + r_) * KH + c_ * 8;
    const __half* gB = W + (size_t)(n0 + r_) * KH + c_ * 8;
    const uint32_t s0 = smem_u32(smbuf);
    const uint32_t stOff = (r_ * 5 + c_) * 16;

#define LOAD_SLAB(st, k0)                                                    \
    do {                                                                     \
        uint32_t ab = s0 + (st) * STAGEB;                                    \
        uint32_t bb = ab + ASZ;                                              \
        cp16(ab + stOff, gA + (k0));                                         \
        cp16(ab + stOff + 64 * 5 * 16, gA + (k0) + (size_t)64 * KH);         \
        cp16(bb + stOff, gB + (k0));                                         \
        cp16(bb + stOff + 64 * 5 * 16, gB + (k0) + (size_t)64 * KH);         \
    } while (0)

    const int NS = KH / 32;   // 16 slabs

    // prologue: stages 0..2
#pragma unroll
    for (int i = 0; i < 3; i++) {
        LOAD_SLAB(i, i * 32);
        CP_COMMIT();
    }

    const int aRow = wm * 32 + (lane & 15);
    const int aChk = lane >> 4;
    const int bRowBase = wn * 64 + (lane & 7) + ((lane >> 4) << 3);
    const int bChk = (lane >> 3) & 1;

    for (int s = 0; s < NS; s++) {
        const int st = s & 3;
        CP_WAIT2();               // slab s resident
        __syncthreads();

        const uint32_t aBase = s0 + st * STAGEB;
        const uint32_t bBase = aBase + ASZ;
#pragma unroll
        for (int kk = 0; kk < 2; kk++) {
            uint32_t af[2][4];
#pragma unroll
            for (int mt = 0; mt < 2; mt++) {
                uint32_t ad = aBase +
                    ((aRow + mt * 16) * 5 + kk * 2 + aChk) * 16;
                ldsm4(af[mt][0], af[mt][1], af[mt][2], af[mt][3], ad);
            }
            uint32_t bf[8][2];
#pragma unroll
            for (int pr = 0; pr < 4; pr++) {
                uint32_t bd = bBase +
                    ((bRowBase + pr * 16) * 5 + kk * 2 + bChk) * 16;
                uint32_t r0, r1, r2, r3;
                ldsm4(r0, r1, r2, r3, bd);
                bf[2 * pr][0] = r0; bf[2 * pr][1] = r1;
                bf[2 * pr + 1][0] = r2; bf[2 * pr + 1][1] = r3;
            }
#pragma unroll
            for (int mt = 0; mt < 2; mt++)
#pragma unroll
                for (int nt = 0; nt < 8; nt++)
                    mma16816(acc[mt][nt], af[mt], bf[nt]);
        }

        // load slab s+3 into the buffer that held slab s-1 (safe: consumed)
        if (s + 3 < NS) LOAD_SLAB((s + 3) & 3, (s + 3) * 32);
        CP_COMMIT();
    }

    const int g  = lane >> 2;
    const int t4 = lane & 3;
#pragma unroll
    for (int nt = 0; nt < 8; nt++) {
        const int col = n0 + wn * 64 + nt * 8 + 2 * t4;
        float2 bb = *(const float2*)(bias + col);
#pragma unroll
        for (int mt = 0; mt < 2; mt++) {
            size_t row0 = m0 + wm * 32 + mt * 16 + g;
            float v00 = acc[mt][nt][0] + bb.x, v01 = acc[mt][nt][1] + bb.y;
            float v10 = acc[mt][nt][2] + bb.x, v11 = acc[mt][nt][3] + bb.y;
            if constexpr (sizeof(OT) == 4) {
                *(float2*)((float*)C + row0 * N + col) = make_float2(v00, v01);
                *(float2*)((float*)C + (row0 + 8) * N + col) = make_float2(v10, v11);
            } else {
                *(__half2*)((__half*)C + row0 * N + col) =
                    __floats2half2_rn(v00, v01);
                *(__half2*)((__half*)C + (row0 + 8) * N + col) =
                    __floats2half2_rn(v10, v11);
            }
        }
    }
#undef LOAD_SLAB
}

// ======================= tensor-core attention ==============================
__global__ void __launch_bounds__(64)
attn_mma(const __half* __restrict__ qkv, const float* __restrict__ table,
         __half* __restrict__ outp) {
    __shared__ __align__(16) __half Qs[64 * 40];
    __shared__ __align__(16) __half Ks[64 * 40];
    __shared__ __align__(16) __half Vs[64 * 40];
    __shared__ float Bs[169];
    __shared__ int   rowi[49];
    __shared__ int   cinfo[64];

    const int tid  = threadIdx.x;
    const int w    = tid >> 5;
    const int lane = tid & 31;
    const int head = blockIdx.x & 7;
    const int win  = blockIdx.x >> 3;
    const int b    = win >> 6;
    const int wr   = (win >> 3) & 7;
    const int wc   = win & 7;

    if (tid < 49) {
        int ih = tid / 7, iw = tid - ih * 7;
        int oh = wr * 7 + ih + 3; if (oh >= 56) oh -= 56;
        int ow = wc * 7 + iw + 3; if (ow >= 56) ow -= 56;
        rowi[tid] = (b * 56 + oh) * 56 + ow;
    }
    {
        int j = tid;
        int jh = j / 7, jw = j - jh * 7;
        int hj = wr * 7 + jh, wj = wc * 7 + jw;
        int rj = ((hj < 49) ? 0 : (hj < 53 ? 1 : 2)) * 3 +
                 ((wj < 49) ? 0 : (wj < 53 ? 1 : 2));
        cinfo[j] = (jh * 13 + jw) | (rj << 8) | ((j < 49 ? 0 : 1) << 15);
    }
    for (int t = tid; t < 169; t += 64) Bs[t] = table[t * 8 + head];
    for (int idx = tid; idx < 180; idx += 64) {
        int mat = idx / 60, rem = idx - mat * 60;
        int r = 49 + (rem >> 2), q = rem & 3;
        __half* base = (mat == 0) ? Qs : (mat == 1) ? Ks : Vs;
        *(uint4*)(base + r * 40 + q * 8) = make_uint4(0, 0, 0, 0);
    }
    __syncthreads();

    for (int idx = tid; idx < 196; idx += 64) {
        int p = idx >> 2, q = idx & 3;
        const __half* src = qkv + (size_t)rowi[p] * 768 + head * 32 + q * 8;
        *(uint4*)(Qs + p * 40 + q * 8) = *(const uint4*)(src);
        *(uint4*)(Ks + p * 40 + q * 8) = *(const uint4*)(src + 256);
        *(uint4*)(Vs + p * 40 + q * 8) = *(const uint4*)(src + 512);
    }
    __syncthreads();

    const uint32_t sQ = smem_u32(Qs), sK = smem_u32(Ks), sV = smem_u32(Vs);

    uint32_t aQ[2][2][4];
#pragma unroll
    for (int mt = 0; mt < 2; mt++)
#pragma unroll
        for (int kk = 0; kk < 2; kk++) {
            int row = w * 32 + mt * 16 + (lane & 15);
            uint32_t ad = sQ + row * 80 + (kk * 2 + (lane >> 4)) * 16;
            ldsm4(aQ[mt][kk][0], aQ[mt][kk][1], aQ[mt][kk][2], aQ[mt][kk][3], ad);
        }
    uint32_t bK[2][8][2];
#pragma unroll
    for (int kk = 0; kk < 2; kk++)
#pragma unroll
        for (int pr = 0; pr < 4; pr++) {
            int row = pr * 16 + (lane & 7) + ((lane >> 4) << 3);
            uint32_t ad = sK + row * 80 + (kk * 2 + ((lane >> 3) & 1)) * 16;
            uint32_t r0, r1, r2, r3;
            ldsm4(r0, r1, r2, r3, ad);
            bK[kk][2 * pr][0] = r0;     bK[kk][2 * pr][1] = r1;
            bK[kk][2 * pr + 1][0] = r2; bK[kk][2 * pr + 1][1] = r3;
        }
    float s[2][8][4];
#pragma unroll
    for (int mt = 0; mt < 2; mt++)
#pragma unroll
        for (int nt = 0; nt < 8; nt++) {
            s[mt][nt][0] = s[mt][nt][1] = s[mt][nt][2] = s[mt][nt][3] = 0.f;
            mma16816(s[mt][nt], aQ[mt][0], bK[0][nt]);
            mma16816(s[mt][nt], aQ[mt][1], bK[1][nt]);
        }

    const int g  = lane >> 2;
    const int t4 = lane & 3;
    const float scale = 0.17677669529663687f;

    int cp[16];
#pragma unroll
    for (int nt = 0; nt < 8; nt++) {
        cp[2 * nt]     = cinfo[nt * 8 + 2 * t4];
        cp[2 * nt + 1] = cinfo[nt * 8 + 2 * t4 + 1];
    }
    int   rb[2][2], ri[2][2];
    bool  rv[2][2];
#pragma unroll
    for (int mt = 0; mt < 2; mt++)
#pragma unroll
        for (int h = 0; h < 2; h++) {
            int i = w * 32 + mt * 16 + g + 8 * h;
            rv[mt][h] = (i < 49);
            int ih = i / 7, iw = i - ih * 7;
            if (!rv[mt][h]) { ih = 0; iw = 0; }
            rb[mt][h] = (ih + 6) * 13 + iw + 6;
            int hh = wr * 7 + ih, vv = wc * 7 + iw;
            ri[mt][h] = ((hh < 49) ? 0 : (hh < 53 ? 1 : 2)) * 3 +
                        ((vv < 49) ? 0 : (vv < 53 ? 1 : 2));
        }
#pragma unroll
    for (int mt = 0; mt < 2; mt++)
#pragma unroll
        for (int nt = 0; nt < 8; nt++)
#pragma unroll
            for (int e = 0; e < 4; e++) {
                int h = e >> 1, cs = e & 1;
                float v;
                if (!rv[mt][h]) v = 0.f;
                else {
                    int ci = cp[2 * nt + cs];
                    if (ci >> 15) v = -1e4f;
                    else {
                        v = s[mt][nt][e] * scale + Bs[rb[mt][h] - (ci & 0xFF)];
                        if (((ci >> 8) & 0xF) != ri[mt][h]) v -= 100.f;
                    }
                }
                s[mt][nt][e] = v;
            }

    float zinv[2][2];
#pragma unroll
    for (int mt = 0; mt < 2; mt++)
#pragma unroll
        for (int h = 0; h < 2; h++) {
            float m = -1e30f;
#pragma unroll
            for (int nt = 0; nt < 8; nt++) {
                m = fmaxf(m, s[mt][nt][2 * h]);
                m = fmaxf(m, s[mt][nt][2 * h + 1]);
            }
            m = fmaxf(m, __shfl_xor_sync(0xffffffffu, m, 1));
            m = fmaxf(m, __shfl_xor_sync(0xffffffffu, m, 2));
            float sum = 0.f;
#pragma unroll
            for (int nt = 0; nt < 8; nt++) {
                float e0 = __expf(s[mt][nt][2 * h] - m);
                float e1 = __expf(s[mt][nt][2 * h + 1] - m);
                s[mt][nt][2 * h] = e0;
                s[mt][nt][2 * h + 1] = e1;
                sum += e0 + e1;
            }
            sum += __shfl_xor_sync(0xffffffffu, sum, 1);
            sum += __shfl_xor_sync(0xffffffffu, sum, 2);
            zinv[mt][h] = 1.0f / sum;
        }

    uint32_t aP[2][4][4];
#pragma unroll
    for (int mt = 0; mt < 2; mt++)
#pragma unroll
        for (int kt = 0; kt < 4; kt++) {
            aP[mt][kt][0] = h2u(__floats2half2_rn(s[mt][2 * kt][0],
                                                  s[mt][2 * kt][1]));
            aP[mt][kt][1] = h2u(__floats2half2_rn(s[mt][2 * kt][2],
                                                  s[mt][2 * kt][3]));
            aP[mt][kt][2] = h2u(__floats2half2_rn(s[mt][2 * kt + 1][0],
                                                  s[mt][2 * kt + 1][1]));
            aP[mt][kt][3] = h2u(__floats2half2_rn(s[mt][2 * kt + 1][2],
                                                  s[mt][2 * kt + 1][3]));
        }

    uint32_t bV[4][4][2];
#pragma unroll
    for (int kt = 0; kt < 4; kt++)
#pragma unroll
        for (int nh = 0; nh < 2; nh++) {
            int row = kt * 16 + (lane & 7) + (((lane >> 3) & 1) << 3);
            uint32_t ad = sV + row * 80 + nh * 32 + ((lane >> 4) << 4);
            uint32_t r0, r1, r2, r3;
            ldsm4t(r0, r1, r2, r3, ad);
            bV[kt][2 * nh][0] = r0;     bV[kt][2 * nh][1] = r1;
            bV[kt][2 * nh + 1][0] = r2; bV[kt][2 * nh + 1][1] = r3;
        }

    float o[2][4][4];
#pragma unroll
    for (int mt = 0; mt < 2; mt++)
#pragma unroll
        for (int vn = 0; vn < 4; vn++) {
            o[mt][vn][0] = o[mt][vn][1] = o[mt][vn][2] = o[mt][vn][3] = 0.f;
#pragma unroll
            for (int kt = 0; kt < 4; kt++)
                mma16816(o[mt][vn], aP[mt][kt], bV[kt][vn]);
        }

#pragma unroll
    for (int mt = 0; mt < 2; mt++)
#pragma unroll
        for (int h = 0; h < 2; h++) {
            int i = w * 32 + mt * 16 + g + 8 * h;
            if (i >= 49) continue;
            float rz = zinv[mt][h];
            __half* dst = outp + (size_t)rowi[i] * KH + head * 32;
#pragma unroll
            for (int vn = 0; vn < 4; vn++) {
                int col = vn * 8 + 2 * t4;
                float v0 = o[mt][vn][2 * h] * rz;
                float v1 = o[mt][vn][2 * h + 1] * rz;
                __half h0 = __float2half_rn(v0), h1 = __float2half_rn(v1);
                __half l0 = __float2half_rn(v0 - __half2float(h0));
                __half l1 = __float2half_rn(v1 - __half2float(h1));
                *(__half2*)(dst + col)       = __halves2half2(h0, h1);
                *(__half2*)(dst + 256 + col) = __halves2half2(l0, l1);
            }
        }
}

// ---------------------------------------------------------------------------
extern "C" void kernel_launch(void* const* d_in, const int* in_sizes, int n_in,
                              void* d_out, int out_size) {
    const float* x      = (const float*)d_in[0];
    const float* qkv_w  = (const float*)d_in[1];
    const float* qkv_b  = (const float*)d_in[2];
    const float* proj_w = (const float*)d_in[3];
    const float* proj_b = (const float*)d_in[4];
    const float* table  = (const float*)d_in[5];
    float* out = (float*)d_out;

    void *qkv_p, *xcat_p, *acat_p, *wq_p, *wp_p;
    cudaGetSymbolAddress(&qkv_p,  g_qkv);
    cudaGetSymbolAddress(&xcat_p, g_xcat);
    cudaGetSymbolAddress(&acat_p, g_acat);
    cudaGetSymbolAddress(&wq_p,   g_wq);
    cudaGetSymbolAddress(&wp_p,   g_wp);
    __half* qkv  = (__half*)qkv_p;
    __half* xcat = (__half*)xcat_p;
    __half* acat = (__half*)acat_p;
    __half* wq   = (__half*)wq_p;
    __half* wp   = (__half*)wp_p;

    static bool attr_done = false;
    if (!attr_done) {
        cudaFuncSetAttribute(gemm_mma<__half>,
                             cudaFuncAttributeMaxDynamicSharedMemorySize,
                             GEMM_SMEM);
        cudaFuncSetAttribute(gemm_mma<float>,
                             cudaFuncAttributeMaxDynamicSharedMemorySize,
                             GEMM_SMEM);
        attr_done = true;
    }

    convert_split<<<(M_ROWS * 64 + 255) / 256, 256>>>(x, xcat, M_ROWS, 0);
    convert_split<<<(768 * 64 + 255) / 256, 256>>>(qkv_w, wq, 768, 1);
    convert_split<<<(256 * 64 + 255) / 256, 256>>>(proj_w, wp, 256, 1);

    dim3 gq(768 / 128, M_ROWS / 128);
    gemm_mma<__half><<<gq, 256, GEMM_SMEM>>>(xcat, wq, qkv_b, qkv, 768);

    attn_mma<<<2048 * 8, 64>>>(qkv, table, acat);

    dim3 gp(256 / 128, M_ROWS / 128);
    gemm_mma<float><<<gp, 256, GEMM_SMEM>>>(acat, wp, proj_b, out, 256);
}